// round 14
// baseline (speedup 1.0000x reference)
#include <cuda_runtime.h>
#include <cstdint>

#define NN 100000
#define EE 1600000
#define EV (EE / 4)
#define C 64
#define HIDN 128
#define NEG 0.2f

#define G1  592            // K1/K2 grid (4 blocks/SM, one wave)
#define NT  256
#define NW  8

#define MAX_L2   4096
#define MAX_S1   4100
#define MAX_L1   262144
#define MAX_DEG2 144
#define HBITS    11
#define HSIZE    (1 << HBITS)
#define HMASK    (HSIZE - 1)
#define HASH_CAP 1024
#define LCAP     512

// ---- scratch (device globals, zero at load; K2 tail restores zeros) -------
__device__ int      g_slot[NN];
__device__ int      g_l2e[MAX_L2];
__device__ int      g_l2cnt;
__device__ int      g_s1[MAX_S1];
__device__ int      g_s1cnt;
__device__ float4   g_l1pack[MAX_L1];
__device__ int      g_l1cnt;
__device__ float    g_eapart[G1];
__device__ float    g_easum;
__device__ float    g_xr[MAX_S1 * C];
__device__ float    g_ndenom[MAX_S1];
__device__ float    g_nacc[MAX_S1 * C];
__device__ float    g_h1[MAX_S1 * C];
__device__ unsigned g_done1;
__device__ unsigned g_done2;

__device__ __forceinline__ float wred(float v) {
#pragma unroll
    for (int off = 16; off > 0; off >>= 1)
        v += __shfl_xor_sync(0xffffffffu, v, off);
    return v;
}
__device__ __forceinline__ unsigned hh(int v) {
    return ((unsigned)v * 2654435761u) >> (32 - HBITS);
}

// ======================= K1: scan A + epilogue B ===========================
__global__ void __launch_bounds__(NT) k1(
    const float* __restrict__ x,   const int* __restrict__ ei,
    const float* __restrict__ ea,  const int* __restrict__ tgtp,
    const float* __restrict__ Wl1, const float* __restrict__ bl1,
    const float* __restrict__ Wr1, const float* __restrict__ br1,
    const float* __restrict__ We1, const float* __restrict__ att1)
{
    const int tid  = threadIdx.x;
    const int bid  = blockIdx.x;
    const int lane = tid & 31;
    const int wid  = tid >> 5;
    const int gid  = bid * NT + tid;
    const int c0 = lane, c1 = lane + 32;

    __shared__ float s_w[NW];
    __shared__ float s_Wl[2 * C], s_Wr[2 * C], s_We[C], s_att[C], s_bl[C], s_br[C];
    __shared__ float s_easum;
    __shared__ int   s_elect;

    const int tgt = tgtp[0];
    const int4*   dst4 = reinterpret_cast<const int4*>(ei + EE);
    const float4* ea4  = reinterpret_cast<const float4*>(ea);
    const int stride = G1 * NT;

    if (bid == 0 && tid == 0) {
        if (atomicCAS(&g_slot[tgt], 0, -1) == 0) {
            int p = atomicAdd(&g_s1cnt, 1);
            if (p < MAX_S1) g_s1[p] = tgt;
        }
    }

    float v = 0.f;
    for (int base = gid; base < EV; base += stride * 3) {
        int ii[3]; float4 a[3]; int4 d[3];
#pragma unroll
        for (int u = 0; u < 3; u++) ii[u] = base + u * stride;
#pragma unroll
        for (int u = 0; u < 3; u++) if (ii[u] < EV) a[u] = ea4[ii[u]];
#pragma unroll
        for (int u = 0; u < 3; u++) if (ii[u] < EV) d[u] = dst4[ii[u]];
#pragma unroll
        for (int u = 0; u < 3; u++) {
            if (ii[u] >= EV) continue;
            v += (a[u].x + a[u].y) + (a[u].z + a[u].w);
            int vv[4] = {d[u].x, d[u].y, d[u].z, d[u].w};
#pragma unroll
            for (int q = 0; q < 4; q++) {
                if (vv[q] == tgt) {
                    int e = ii[u] * 4 + q;
                    int p = atomicAdd(&g_l2cnt, 1);
                    if (p < MAX_L2) g_l2e[p] = e;
                    int src = ei[e];
                    if (atomicCAS(&g_slot[src], 0, -1) == 0) {
                        int s = atomicAdd(&g_s1cnt, 1);
                        if (s < MAX_S1) g_s1[s] = src;
                    }
                }
            }
        }
    }
    v = wred(v);
    if (lane == 0) s_w[wid] = v;
    __syncthreads();
    if (tid == 0) {
        float s = 0.f;
#pragma unroll
        for (int w = 0; w < NW; w++) s += s_w[w];
        g_eapart[bid] = s;
    }

    // election: last block to finish does phase B
    __syncthreads();
    if (tid == 0) {
        __threadfence();
        unsigned t = atomicAdd(&g_done1, 1u);
        s_elect = (t == G1 - 1u) ? 1 : 0;
        if (s_elect) __threadfence();
    }
    __syncthreads();
    if (!s_elect) return;

    // ---- epilogue B (elected block) ----
    if (tid < C) {
        s_Wl[tid] = Wl1[tid]; s_Wl[C + tid] = Wl1[C + tid];
        s_Wr[tid] = Wr1[tid]; s_Wr[C + tid] = Wr1[C + tid];
        s_We[tid] = We1[tid]; s_att[tid] = att1[tid];
        s_bl[tid] = bl1[tid]; s_br[tid] = br1[tid];
    }
    {
        float s = 0.f;
        for (int i = tid; i < G1; i += NT) s += g_eapart[i];
        s = wred(s);
        if (lane == 0) s_w[wid] = s;
    }
    __syncthreads();
    if (tid == 0) {
        float s = 0.f;
#pragma unroll
        for (int w = 0; w < NW; w++) s += s_w[w];
        g_easum = s;
        s_easum = s;
    }
    __syncthreads();

    const int sc1 = min(g_s1cnt, MAX_S1);
    for (int i = tid; i < sc1; i += NT) g_slot[g_s1[i]] = i + 1;
    __syncthreads();
    const float eam = s_easum * (1.f / (float)EE);
    for (int s = wid; s < sc1; s += NW) {
        int nd = g_s1[s];
        float x0 = x[2 * nd], x1 = x[2 * nd + 1];
        float xl0 = x0 * s_Wl[c0] + x1 * s_Wl[C + c0] + s_bl[c0];
        float xr0 = x0 * s_Wr[c0] + x1 * s_Wr[C + c0] + s_br[c0];
        float xl1 = x0 * s_Wl[c1] + x1 * s_Wl[C + c1] + s_bl[c1];
        float xr1 = x0 * s_Wr[c1] + x1 * s_Wr[C + c1] + s_br[c1];
        g_xr[s * C + c0] = xr0;
        g_xr[s * C + c1] = xr1;
        float t0 = xl0 + xr0 + eam * s_We[c0];
        float t1 = xl1 + xr1 + eam * s_We[c1];
        t0 = t0 >= 0.f ? t0 : NEG * t0;
        t1 = t1 >= 0.f ? t1 : NEG * t1;
        float scv = wred(t0 * s_att[c0] + t1 * s_att[c1]);
        float w = expf(scv);
        g_nacc[s * C + c0] = w * xl0;
        g_nacc[s * C + c1] = w * xl1;
        if (lane == 0) g_ndenom[s] = w;
    }
}

// ======================= K2: scan C + tail F ===============================
__global__ void __launch_bounds__(NT) k2(
    const float* __restrict__ x,   const int* __restrict__ ei,
    const float* __restrict__ ea,  const int* __restrict__ tgtp,
    const float* __restrict__ Wl1, const float* __restrict__ bl1,
    const float* __restrict__ b1,
    const float* __restrict__ Wl2, const float* __restrict__ bl2,
    const float* __restrict__ Wr2, const float* __restrict__ br2,
    const float* __restrict__ We2, const float* __restrict__ att2,
    const float* __restrict__ b2,
    const float* __restrict__ Wf,  const float* __restrict__ bf,
    const float* __restrict__ We1, const float* __restrict__ att1,
    float* __restrict__ out)
{
    const int tid  = threadIdx.x;
    const int bid  = blockIdx.x;
    const int lane = tid & 31;
    const int wid  = tid >> 5;
    const int gid  = bid * NT + tid;
    const int c0 = lane, c1 = lane + 32;

    // 36KB buffer: hash keys(8K)+slots(8K)+packs(8K); tail aliases s_xl(36K)
    __shared__ __align__(16) char s_big[MAX_DEG2 * C * 4];
    int*    s_hkey  = (int*)s_big;
    int*    s_hslot = (int*)(s_big + HSIZE * 4);
    float4* s_pack  = (float4*)(s_big + 2 * HSIZE * 4);
    float*  s_xl    = (float*)s_big;

    __shared__ float s_xr[C];
    __shared__ float s_h2[C];
    __shared__ float s_sc[MAX_DEG2];
    __shared__ float s_Wl[2 * C], s_We[C], s_att[C], s_bl[C];
    __shared__ int   s_lcnt;
    __shared__ int   s_elect;

    const int tgt = tgtp[0];
    const int4* dst4 = reinterpret_cast<const int4*>(ei + EE);
    const int stride = G1 * NT;

    if (tid < C) {
        s_Wl[tid] = Wl1[tid]; s_Wl[C + tid] = Wl1[C + tid];
        s_We[tid] = We1[tid]; s_att[tid] = att1[tid];
        s_bl[tid] = bl1[tid];
    }
    if (tid == 0) s_lcnt = 0;

    const int  sc1      = min(g_s1cnt, MAX_S1);
    const bool use_hash = (sc1 <= HASH_CAP);

    if (use_hash) {
        for (int i = tid; i < HSIZE; i += NT) s_hkey[i] = -1;
        __syncthreads();
        for (int i = tid; i < sc1; i += NT) {
            int v = g_s1[i];
            unsigned h = hh(v);
            while (atomicCAS(&s_hkey[h], -1, v) != -1) h = (h + 1) & HMASK;
            s_hslot[h] = i;
        }
    }
    __syncthreads();

    for (int base = gid; base < EV; base += stride * 3) {
        int ii[3]; int4 d[3];
#pragma unroll
        for (int u = 0; u < 3; u++) ii[u] = base + u * stride;
#pragma unroll
        for (int u = 0; u < 3; u++) if (ii[u] < EV) d[u] = dst4[ii[u]];
#pragma unroll
        for (int u = 0; u < 3; u++) {
            if (ii[u] >= EV) continue;
            int vv[4] = {d[u].x, d[u].y, d[u].z, d[u].w};
#pragma unroll
            for (int q = 0; q < 4; q++) {
                int dstv = vv[q];
                int slot;
                if (use_hash) {
                    slot = -1;
                    unsigned h = hh(dstv);
                    while (true) {
                        int e = s_hkey[h];
                        if (e == dstv) { slot = s_hslot[h]; break; }
                        if (e == -1) break;
                        h = (h + 1) & HMASK;
                    }
                } else {
                    slot = g_slot[dstv] - 1;      // B done in K1; safe
                }
                if (slot >= 0) {
                    int e = ii[u] * 4 + q;
                    int srcv = ei[e];
                    float eav = ea[e];
                    const float2 xj = *reinterpret_cast<const float2*>(x + 2 * srcv);
                    float4 pk = make_float4(xj.x, xj.y, eav, __int_as_float(slot));
                    int p = atomicAdd(&s_lcnt, 1);
                    if (p < LCAP) s_pack[p] = pk;
                    else { int q2 = atomicAdd(&g_l1cnt, 1); if (q2 < MAX_L1) g_l1pack[q2] = pk; }
                }
            }
        }
    }
    __syncthreads();

    // process local hits (no wait needed — B completed in K1)
    {
        int cnt = min(s_lcnt, LCAP);
        for (int idx = wid; idx < cnt; idx += NW) {
            float4 pk = s_pack[idx];
            int slot = __float_as_int(pk.w);
            float xl0 = pk.x * s_Wl[c0] + pk.y * s_Wl[C + c0] + s_bl[c0];
            float xl1 = pk.x * s_Wl[c1] + pk.y * s_Wl[C + c1] + s_bl[c1];
            float t0 = xl0 + g_xr[slot * C + c0] + pk.z * s_We[c0];
            float t1 = xl1 + g_xr[slot * C + c1] + pk.z * s_We[c1];
            t0 = t0 >= 0.f ? t0 : NEG * t0;
            t1 = t1 >= 0.f ? t1 : NEG * t1;
            float scv = wred(t0 * s_att[c0] + t1 * s_att[c1]);
            float w = expf(scv);
            atomicAdd(&g_nacc[slot * C + c0], w * xl0);
            atomicAdd(&g_nacc[slot * C + c1], w * xl1);
            if (lane == 0) atomicAdd(&g_ndenom[slot], w);
        }
    }

    // election: last block runs the tail
    __syncthreads();
    if (tid == 0) {
        __threadfence();
        unsigned t = atomicAdd(&g_done2, 1u);
        s_elect = (t == G1 - 1u) ? 1 : 0;
        if (s_elect) __threadfence();
    }
    __syncthreads();
    if (!s_elect) return;

    // ---- tail (elected block) ----
    {
        int m1 = min(g_l1cnt, MAX_L1);   // spill packs (normally zero)
        for (int idx = wid; idx < m1; idx += NW) {
            float4 pk = g_l1pack[idx];
            int slot = __float_as_int(pk.w);
            float xl0 = pk.x * s_Wl[c0] + pk.y * s_Wl[C + c0] + s_bl[c0];
            float xl1 = pk.x * s_Wl[c1] + pk.y * s_Wl[C + c1] + s_bl[c1];
            float t0 = xl0 + g_xr[slot * C + c0] + pk.z * s_We[c0];
            float t1 = xl1 + g_xr[slot * C + c1] + pk.z * s_We[c1];
            t0 = t0 >= 0.f ? t0 : NEG * t0;
            t1 = t1 >= 0.f ? t1 : NEG * t1;
            float scv = wred(t0 * s_att[c0] + t1 * s_att[c1]);
            float w = expf(scv);
            atomicAdd(&g_nacc[slot * C + c0], w * xl0);
            atomicAdd(&g_nacc[slot * C + c1], w * xl1);
            if (lane == 0) atomicAdd(&g_ndenom[slot], w);
        }
    }
    __syncthreads();

    for (int i = tid; i < sc1 * C; i += NT) {
        float v = g_nacc[i] / g_ndenom[i >> 6] + b1[i & 63];
        g_h1[i] = fmaxf(v, 0.f);
    }
    __syncthreads();

    const int   ts      = g_slot[tgt] - 1;
    const float ea_mean = g_easum * (1.f / (float)EE);

    if (tid < C) {
        const float* h1t = &g_h1[ts * C];
        float a0 = 0.f, a1 = 0.f, a2 = 0.f, a3 = 0.f;
#pragma unroll
        for (int k = 0; k < C; k += 4) {
            a0 += h1t[k]     * Wr2[(k)     * C + tid];
            a1 += h1t[k + 1] * Wr2[(k + 1) * C + tid];
            a2 += h1t[k + 2] * Wr2[(k + 2) * C + tid];
            a3 += h1t[k + 3] * Wr2[(k + 3) * C + tid];
        }
        s_xr[tid] = br2[tid] + ((a0 + a1) + (a2 + a3));
    }
    __syncthreads();

    const int m2  = min(g_l2cnt, MAX_L2);
    const int deg = min(m2 + 1, MAX_DEG2);
    for (int idx = wid; idx < deg; idx += NW) {
        int j; float eav;
        if (idx == 0) { j = tgt; eav = ea_mean; }
        else          { int e = g_l2e[idx - 1]; j = ei[e]; eav = ea[e]; }
        const float* hrow = &g_h1[(g_slot[j] - 1) * C];
        float xla = bl2[c0], xlb = bl2[c1];
#pragma unroll 8
        for (int k = 0; k < C; k++) {
            float h = hrow[k];
            xla += h * Wl2[k * C + c0];
            xlb += h * Wl2[k * C + c1];
        }
        float ta = xla + s_xr[c0] + eav * We2[c0];
        float tb = xlb + s_xr[c1] + eav * We2[c1];
        ta = ta >= 0.f ? ta : NEG * ta;
        tb = tb >= 0.f ? tb : NEG * tb;
        float s = wred(ta * att2[c0] + tb * att2[c1]);
        s_xl[idx * C + c0] = xla;
        s_xl[idx * C + c1] = xlb;
        if (lane == 0) s_sc[idx] = s;
    }
    __syncthreads();

    if (tid < C) {
        float smax = -3.4e38f;
        for (int k = 0; k < deg; k++) smax = fmaxf(smax, s_sc[k]);
        float denom = 0.f, acc = 0.f;
        for (int k = 0; k < deg; k++) {
            float w = expf(s_sc[k] - smax);
            denom += w;
            acc   += w * s_xl[k * C + tid];
        }
        s_h2[tid] = fmaxf(acc / denom + b2[tid], 0.f);
    }
    __syncthreads();

    if (tid < HIDN) {
        float o = bf[tid];
#pragma unroll
        for (int k = 0; k < C; k++) o += s_h2[k] * Wf[k * HIDN + tid];
        out[tid] = o;
    }

    // cleanup: restore zero-state for graph replay
    __syncthreads();
    for (int i = tid; i < sc1; i += NT) g_slot[g_s1[i]] = 0;
    __syncthreads();
    if (tid == 0) {
        g_l2cnt = 0; g_s1cnt = 0; g_l1cnt = 0;
        g_done1 = 0; g_done2 = 0;
        __threadfence();
    }
}

extern "C" void kernel_launch(void* const* d_in, const int* in_sizes, int n_in,
                              void* d_out, int out_size) {
    const float* x    = (const float*)d_in[0];
    const int*   ei   = (const int*)d_in[1];
    const float* ea   = (const float*)d_in[2];
    const int*   tgt  = (const int*)d_in[3];
    const float* Wl1  = (const float*)d_in[4];
    const float* bl1  = (const float*)d_in[5];
    const float* Wr1  = (const float*)d_in[6];
    const float* br1  = (const float*)d_in[7];
    const float* We1  = (const float*)d_in[8];
    const float* att1 = (const float*)d_in[9];
    const float* b1   = (const float*)d_in[10];
    const float* Wl2  = (const float*)d_in[11];
    const float* bl2  = (const float*)d_in[12];
    const float* Wr2  = (const float*)d_in[13];
    const float* br2  = (const float*)d_in[14];
    const float* We2  = (const float*)d_in[15];
    const float* att2 = (const float*)d_in[16];
    const float* b2   = (const float*)d_in[17];
    const float* Wf   = (const float*)d_in[18];
    const float* bf   = (const float*)d_in[19];
    float* out = (float*)d_out;

    k1<<<G1, NT>>>(x, ei, ea, tgt, Wl1, bl1, Wr1, br1, We1, att1);
    k2<<<G1, NT>>>(x, ei, ea, tgt, Wl1, bl1, b1,
                   Wl2, bl2, Wr2, br2, We2, att2, b2,
                   Wf, bf, We1, att1, out);
}

// round 15
// speedup vs baseline: 1.3719x; 1.3719x over previous
#include <cuda_runtime.h>
#include <cstdint>

#define NN 100000
#define EE 1600000
#define EV (EE / 4)
#define C 64
#define HIDN 128
#define NEG 0.2f

#define NB 148
#define NT 1024
#define NWB 32
#define NGRP 16            // two-level barrier groups

#define MAX_L2   4096
#define MAX_S1   4100
#define MAX_L1   262144
#define MAX_DEG2 144
#define HBITS    11
#define HSIZE    (1 << HBITS)
#define HMASK    (HSIZE - 1)
#define HASH_CAP 1024
#define LCAP     512

// ---- scratch (device globals, zero at load; elected block restores zeros) --
__device__ int      g_slot[NN];
__device__ int      g_l2e[MAX_L2];
__device__ int      g_l2cnt;
__device__ int      g_s1[MAX_S1];
__device__ int      g_s1cnt;
__device__ float4   g_l1pack[MAX_L1];
__device__ int      g_l1cnt;
__device__ float    g_eapart[NB];
__device__ float    g_easum;
__device__ float    g_xr[MAX_S1 * C];
__device__ float    g_ndenom[MAX_S1];
__device__ float    g_nacc[MAX_S1 * C];
__device__ float    g_h1[MAX_S1 * C];
__device__ unsigned g_barg[NGRP];     // padded contention: distinct addresses
__device__ unsigned g_barroot;
__device__ unsigned g_bflag;
__device__ unsigned g_done;
__device__ float    g_warmsink;

__device__ __forceinline__ float wred(float v) {
#pragma unroll
    for (int off = 16; off > 0; off >>= 1)
        v += __shfl_xor_sync(0xffffffffu, v, off);
    return v;
}
__device__ __forceinline__ unsigned hh(int v) {
    return ((unsigned)v * 2654435761u) >> (32 - HBITS);
}
// two-level grid barrier: groups of <=10 arrive on distinct counters;
// group-closers arrive on root; everyone polls root.
__device__ __forceinline__ void gbar2(int bid) {
    __syncthreads();
    if (threadIdx.x == 0) {
        int g   = bid & (NGRP - 1);
        int gsz = (NB / NGRP) + ((g < (NB % NGRP)) ? 1 : 0);
        __threadfence();
        unsigned t = atomicAdd(&g_barg[g], 1u);
        if (t == (unsigned)(gsz - 1)) atomicAdd(&g_barroot, 1u);
        while (*((volatile unsigned*)&g_barroot) < NGRP) { }
        __threadfence();
    }
    __syncthreads();
}

__global__ void __launch_bounds__(NT, 1) k_fused(
    const float* __restrict__ x,   const int* __restrict__ ei,
    const float* __restrict__ ea,  const int* __restrict__ tgtp,
    const float* __restrict__ Wl1, const float* __restrict__ bl1,
    const float* __restrict__ Wr1, const float* __restrict__ br1,
    const float* __restrict__ We1, const float* __restrict__ att1,
    const float* __restrict__ b1,
    const float* __restrict__ Wl2, const float* __restrict__ bl2,
    const float* __restrict__ Wr2, const float* __restrict__ br2,
    const float* __restrict__ We2, const float* __restrict__ att2,
    const float* __restrict__ b2,
    const float* __restrict__ Wf,  const float* __restrict__ bf,
    float* __restrict__ out)
{
    const int tid  = threadIdx.x;
    const int bid  = blockIdx.x;
    const int lane = tid & 31;
    const int wid  = tid >> 5;
    const int gid  = bid * NT + tid;
    const int c0 = lane, c1 = lane + 32;

    // big buffer: hash (8KB keys + 8KB slots) + local packs (8KB); F alias
    __shared__ __align__(16) char s_big[MAX_DEG2 * C * 4];
    int*    s_hkey  = (int*)s_big;
    int*    s_hslot = (int*)(s_big + HSIZE * 4);
    float4* s_pack  = (float4*)(s_big + 2 * HSIZE * 4);
    float*  s_xl    = (float*)s_big;

    __shared__ float s_w[NWB];
    __shared__ float s_xr[C];
    __shared__ float s_h2[C];
    __shared__ float s_sc[MAX_DEG2];
    __shared__ float s_Wl[2 * C], s_Wr[2 * C], s_We[C], s_att[C], s_bl[C], s_br[C];
    __shared__ int   s_lcnt;
    __shared__ float s_easum;
    __shared__ int   s_elect;

    const int tgt = tgtp[0];
    const int4*   dst4 = reinterpret_cast<const int4*>(ei + EE);
    const float4* ea4  = reinterpret_cast<const float4*>(ea);
    const int stride = NB * NT;

    // ---- phase A: scan dst+ea immediately --------------------------------
    {
        if (bid == 0 && tid == 0) {
            if (atomicCAS(&g_slot[tgt], 0, -1) == 0) {
                int p = atomicAdd(&g_s1cnt, 1);
                if (p < MAX_S1) g_s1[p] = tgt;
            }
        }
        float v = 0.f;
        for (int base = gid; base < EV; base += stride * 6) {
            int ii[6]; float4 a[6]; int4 d[6];
#pragma unroll
            for (int u = 0; u < 6; u++) ii[u] = base + u * stride;
#pragma unroll
            for (int u = 0; u < 6; u++) if (ii[u] < EV) a[u] = ea4[ii[u]];
#pragma unroll
            for (int u = 0; u < 6; u++) if (ii[u] < EV) d[u] = dst4[ii[u]];
#pragma unroll
            for (int u = 0; u < 6; u++) {
                if (ii[u] >= EV) continue;
                v += (a[u].x + a[u].y) + (a[u].z + a[u].w);
                int vv[4] = {d[u].x, d[u].y, d[u].z, d[u].w};
#pragma unroll
                for (int q = 0; q < 4; q++) {
                    if (vv[q] == tgt) {
                        int e = ii[u] * 4 + q;
                        int p = atomicAdd(&g_l2cnt, 1);
                        if (p < MAX_L2) g_l2e[p] = e;
                        int src = ei[e];
                        if (atomicCAS(&g_slot[src], 0, -1) == 0) {
                            int s = atomicAdd(&g_s1cnt, 1);
                            if (s < MAX_S1) g_s1[s] = src;
                        }
                    }
                }
            }
        }
        // overlap with scan-load drain: layer-1 weights + hash-table init
        if (tid < C) {
            s_Wl[tid] = Wl1[tid]; s_Wl[C + tid] = Wl1[C + tid];
            s_Wr[tid] = Wr1[tid]; s_Wr[C + tid] = Wr1[C + tid];
            s_We[tid] = We1[tid]; s_att[tid] = att1[tid];
            s_bl[tid] = bl1[tid]; s_br[tid] = br1[tid];
        }
        for (int i = tid; i < HSIZE; i += NT) s_hkey[i] = -1;
        if (tid == 0) s_lcnt = 0;
        v = wred(v);
        if (lane == 0) s_w[wid] = v;
        __syncthreads();
        if (tid == 0) {
            float s = 0.f;
#pragma unroll
            for (int w = 0; w < NWB; w++) s += s_w[w];
            g_eapart[bid] = s;
        }
    }
    gbar2(bid);

    const int  sc1      = min(g_s1cnt, MAX_S1);
    const bool use_hash = (sc1 <= HASH_CAP);

    // ---- phase B (block 0 only, concurrent with other blocks' phase C) ----
    if (bid == 0) {
        if (wid == 0) {
            float s = 0.f;
            for (int i = lane; i < NB; i += 32) s += g_eapart[i];
            s = wred(s);
            if (lane == 0) { g_easum = s; s_easum = s; }
        }
        for (int i = tid; i < sc1; i += NT) g_slot[g_s1[i]] = i + 1;
        __syncthreads();
        float eam = s_easum * (1.f / (float)EE);
        for (int s = wid; s < sc1; s += NWB) {
            int nd = g_s1[s];
            float x0 = x[2 * nd], x1 = x[2 * nd + 1];
            float xl0 = x0 * s_Wl[c0] + x1 * s_Wl[C + c0] + s_bl[c0];
            float xr0 = x0 * s_Wr[c0] + x1 * s_Wr[C + c0] + s_br[c0];
            float xl1 = x0 * s_Wl[c1] + x1 * s_Wl[C + c1] + s_bl[c1];
            float xr1 = x0 * s_Wr[c1] + x1 * s_Wr[C + c1] + s_br[c1];
            g_xr[s * C + c0] = xr0;
            g_xr[s * C + c1] = xr1;
            float t0 = xl0 + xr0 + eam * s_We[c0];
            float t1 = xl1 + xr1 + eam * s_We[c1];
            t0 = t0 >= 0.f ? t0 : NEG * t0;
            t1 = t1 >= 0.f ? t1 : NEG * t1;
            float scv = wred(t0 * s_att[c0] + t1 * s_att[c1]);
            float w = expf(scv);
            g_nacc[s * C + c0] = w * xl0;
            g_nacc[s * C + c1] = w * xl1;
            if (lane == 0) g_ndenom[s] = w;
        }
        __syncthreads();
        if (tid == 0) { __threadfence(); atomicExch(&g_bflag, 1u); }
    } else if (bid == 1) {
        // warm layer-2 + head weights into L2 for the tail
        float wv = 0.f;
        for (int i = tid; i < C * C; i += NT) wv += Wl2[i] + Wr2[i];
        for (int i = tid; i < C * HIDN; i += NT) wv += Wf[i];
        if (tid < C) wv += We2[tid] + att2[tid] + b2[tid] + b1[tid] + bl2[tid] + br2[tid];
        if (tid < HIDN) wv += bf[tid];
        if (wv == 1.2345678e30f) g_warmsink = wv;
    }

    // ---- phase C: insert keys (table pre-initialized); scan dst -----------
    {
        if (use_hash) {
            for (int i = tid; i < sc1; i += NT) {
                int v = g_s1[i];
                unsigned h = hh(v);
                while (atomicCAS(&s_hkey[h], -1, v) != -1) h = (h + 1) & HMASK;
                s_hslot[h] = i;
            }
        } else {
            if (tid == 0) {
                while (*((volatile unsigned*)&g_bflag) == 0u) { }
                __threadfence();
            }
        }
        __syncthreads();
        for (int base = gid; base < EV; base += stride * 6) {
            int ii[6]; int4 d[6];
#pragma unroll
            for (int u = 0; u < 6; u++) ii[u] = base + u * stride;
#pragma unroll
            for (int u = 0; u < 6; u++) if (ii[u] < EV) d[u] = dst4[ii[u]];
#pragma unroll
            for (int u = 0; u < 6; u++) {
                if (ii[u] >= EV) continue;
                int vv[4] = {d[u].x, d[u].y, d[u].z, d[u].w};
#pragma unroll
                for (int q = 0; q < 4; q++) {
                    int dstv = vv[q];
                    int slot;
                    if (use_hash) {
                        slot = -1;
                        unsigned h = hh(dstv);
                        while (true) {
                            int e = s_hkey[h];
                            if (e == dstv) { slot = s_hslot[h]; break; }
                            if (e == -1) break;
                            h = (h + 1) & HMASK;
                        }
                    } else {
                        slot = g_slot[dstv] - 1;
                    }
                    if (slot >= 0) {
                        int e = ii[u] * 4 + q;
                        int srcv = ei[e];
                        float eav = ea[e];
                        const float2 xj = *reinterpret_cast<const float2*>(x + 2 * srcv);
                        float4 pk = make_float4(xj.x, xj.y, eav, __int_as_float(slot));
                        int p = atomicAdd(&s_lcnt, 1);
                        if (p < LCAP) s_pack[p] = pk;
                        else { int q2 = atomicAdd(&g_l1cnt, 1); if (q2 < MAX_L1) g_l1pack[q2] = pk; }
                    }
                }
            }
        }
        __syncthreads();
        // blocks with hits wait for phase-B init, then accumulate
        int cnt = min(s_lcnt, LCAP);
        if (cnt > 0) {
            if (tid == 0) {
                while (*((volatile unsigned*)&g_bflag) == 0u) { }
                __threadfence();
            }
            __syncthreads();
            for (int idx = wid; idx < cnt; idx += NWB) {
                float4 pk = s_pack[idx];
                int slot = __float_as_int(pk.w);
                float xl0 = pk.x * s_Wl[c0] + pk.y * s_Wl[C + c0] + s_bl[c0];
                float xl1 = pk.x * s_Wl[c1] + pk.y * s_Wl[C + c1] + s_bl[c1];
                float t0 = xl0 + g_xr[slot * C + c0] + pk.z * s_We[c0];
                float t1 = xl1 + g_xr[slot * C + c1] + pk.z * s_We[c1];
                t0 = t0 >= 0.f ? t0 : NEG * t0;
                t1 = t1 >= 0.f ? t1 : NEG * t1;
                float scv = wred(t0 * s_att[c0] + t1 * s_att[c1]);
                float w = expf(scv);
                atomicAdd(&g_nacc[slot * C + c0], w * xl0);
                atomicAdd(&g_nacc[slot * C + c1], w * xl1);
                if (lane == 0) atomicAdd(&g_ndenom[slot], w);
            }
        }
    }

    // ---- election: LAST block to finish runs the tail ---------------------
    __syncthreads();
    if (tid == 0) {
        __threadfence();
        unsigned t = atomicAdd(&g_done, 1u);
        s_elect = (t == NB - 1u) ? 1 : 0;
        if (s_elect) __threadfence();
    }
    __syncthreads();
    if (!s_elect) return;

    // process global spill packs (normally zero)
    {
        int m1 = min(g_l1cnt, MAX_L1);
        for (int idx = wid; idx < m1; idx += NWB) {
            float4 pk = g_l1pack[idx];
            int slot = __float_as_int(pk.w);
            float xl0 = pk.x * s_Wl[c0] + pk.y * s_Wl[C + c0] + s_bl[c0];
            float xl1 = pk.x * s_Wl[c1] + pk.y * s_Wl[C + c1] + s_bl[c1];
            float t0 = xl0 + g_xr[slot * C + c0] + pk.z * s_We[c0];
            float t1 = xl1 + g_xr[slot * C + c1] + pk.z * s_We[c1];
            t0 = t0 >= 0.f ? t0 : NEG * t0;
            t1 = t1 >= 0.f ? t1 : NEG * t1;
            float scv = wred(t0 * s_att[c0] + t1 * s_att[c1]);
            float w = expf(scv);
            atomicAdd(&g_nacc[slot * C + c0], w * xl0);
            atomicAdd(&g_nacc[slot * C + c1], w * xl1);
            if (lane == 0) atomicAdd(&g_ndenom[slot], w);
        }
    }
    __syncthreads();

    // finalize h1 = relu(acc/denom + b1)
    for (int i = tid; i < sc1 * C; i += NT) {
        float v = g_nacc[i] / g_ndenom[i >> 6] + b1[i & 63];
        g_h1[i] = fmaxf(v, 0.f);
    }
    __syncthreads();

    const int   ts      = g_slot[tgt] - 1;
    const float ea_mean = g_easum * (1.f / (float)EE);

    if (tid < C) {
        const float* h1t = &g_h1[ts * C];
        float a0 = 0.f, a1 = 0.f, a2 = 0.f, a3 = 0.f;
#pragma unroll
        for (int k = 0; k < C; k += 4) {
            a0 += h1t[k]     * Wr2[(k)     * C + tid];
            a1 += h1t[k + 1] * Wr2[(k + 1) * C + tid];
            a2 += h1t[k + 2] * Wr2[(k + 2) * C + tid];
            a3 += h1t[k + 3] * Wr2[(k + 3) * C + tid];
        }
        s_xr[tid] = br2[tid] + ((a0 + a1) + (a2 + a3));
    }
    __syncthreads();

    const int m2  = min(g_l2cnt, MAX_L2);
    const int deg = min(m2 + 1, MAX_DEG2);
    for (int idx = wid; idx < deg; idx += NWB) {
        int j; float eav;
        if (idx == 0) { j = tgt; eav = ea_mean; }
        else          { int e = g_l2e[idx - 1]; j = ei[e]; eav = ea[e]; }
        const float* hrow = &g_h1[(g_slot[j] - 1) * C];
        float xla = bl2[c0], xlb = bl2[c1];
#pragma unroll 8
        for (int k = 0; k < C; k++) {
            float h = hrow[k];
            xla += h * Wl2[k * C + c0];
            xlb += h * Wl2[k * C + c1];
        }
        float ta = xla + s_xr[c0] + eav * We2[c0];
        float tb = xlb + s_xr[c1] + eav * We2[c1];
        ta = ta >= 0.f ? ta : NEG * ta;
        tb = tb >= 0.f ? tb : NEG * tb;
        float s = wred(ta * att2[c0] + tb * att2[c1]);
        s_xl[idx * C + c0] = xla;
        s_xl[idx * C + c1] = xlb;
        if (lane == 0) s_sc[idx] = s;
    }
    __syncthreads();

    if (tid < C) {
        float smax = -3.4e38f;
        for (int k = 0; k < deg; k++) smax = fmaxf(smax, s_sc[k]);
        float denom = 0.f, acc = 0.f;
        for (int k = 0; k < deg; k++) {
            float w = expf(s_sc[k] - smax);
            denom += w;
            acc   += w * s_xl[k * C + tid];
        }
        s_h2[tid] = fmaxf(acc / denom + b2[tid], 0.f);
    }
    __syncthreads();

    if (tid < HIDN) {
        float o = bf[tid];
#pragma unroll
        for (int k = 0; k < C; k++) o += s_h2[k] * Wf[k * HIDN + tid];
        out[tid] = o;
    }

    // ---- cleanup: restore zero-state for graph replay ---------------------
    __syncthreads();
    for (int i = tid; i < sc1; i += NT) g_slot[g_s1[i]] = 0;
    __syncthreads();
    if (tid == 0) {
        g_l2cnt = 0; g_s1cnt = 0; g_l1cnt = 0;
#pragma unroll
        for (int g = 0; g < NGRP; g++) g_barg[g] = 0;
        g_barroot = 0; g_bflag = 0; g_done = 0;
        __threadfence();
    }
}

extern "C" void kernel_launch(void* const* d_in, const int* in_sizes, int n_in,
                              void* d_out, int out_size) {
    const float* x    = (const float*)d_in[0];
    const int*   ei   = (const int*)d_in[1];
    const float* ea   = (const float*)d_in[2];
    const int*   tgt  = (const int*)d_in[3];
    const float* Wl1  = (const float*)d_in[4];
    const float* bl1  = (const float*)d_in[5];
    const float* Wr1  = (const float*)d_in[6];
    const float* br1  = (const float*)d_in[7];
    const float* We1  = (const float*)d_in[8];
    const float* att1 = (const float*)d_in[9];
    const float* b1   = (const float*)d_in[10];
    const float* Wl2  = (const float*)d_in[11];
    const float* bl2  = (const float*)d_in[12];
    const float* Wr2  = (const float*)d_in[13];
    const float* br2  = (const float*)d_in[14];
    const float* We2  = (const float*)d_in[15];
    const float* att2 = (const float*)d_in[16];
    const float* b2   = (const float*)d_in[17];
    const float* Wf   = (const float*)d_in[18];
    const float* bf   = (const float*)d_in[19];
    float* out = (float*)d_out;

    k_fused<<<NB, NT>>>(x, ei, ea, tgt,
                        Wl1, bl1, Wr1, br1, We1, att1, b1,
                        Wl2, bl2, Wr2, br2, We2, att2, b2,
                        Wf, bf, out);
}

// round 16
// speedup vs baseline: 1.5167x; 1.1056x over previous
#include <cuda_runtime.h>
#include <cstdint>

#define NN 100000
#define EE 1600000
#define EV (EE / 4)
#define C 64
#define HIDN 128
#define NEG 0.2f

#define NB 148
#define NT 1024
#define NWB 32

#define MAX_L2   4096
#define MAX_S1   4100
#define MAX_L1   262144
#define MAX_DEG2 144
#define HBITS    11
#define HSIZE    (1 << HBITS)
#define HMASK    (HSIZE - 1)
#define HASH_CAP 1024
#define LCAP     512

// ---- scratch (device globals, zero at load; elected block restores zeros) --
__device__ int      g_slot[NN];
__device__ int      g_l2e[MAX_L2];
__device__ int      g_l2cnt;
__device__ int      g_s1[MAX_S1];
__device__ int      g_s1cnt;
__device__ float4   g_l1pack[MAX_L1];
__device__ int      g_l1cnt;
__device__ float    g_eapart[NB];
__device__ float    g_easum;
__device__ float    g_xr[MAX_S1 * C];
__device__ float    g_ndenom[MAX_S1];
__device__ float    g_nacc[MAX_S1 * C];
__device__ float    g_h1[MAX_S1 * C];
__device__ unsigned g_barc;
__device__ unsigned g_bflag;
__device__ unsigned g_done;
__device__ float    g_warmsink;

__device__ __forceinline__ float wred(float v) {
#pragma unroll
    for (int off = 16; off > 0; off >>= 1)
        v += __shfl_xor_sync(0xffffffffu, v, off);
    return v;
}
__device__ __forceinline__ unsigned hh(int v) {
    return ((unsigned)v * 2654435761u) >> (32 - HBITS);
}
__device__ __forceinline__ void gbar0() {
    __syncthreads();
    if (threadIdx.x == 0) {
        __threadfence();
        atomicAdd(&g_barc, 1u);
        while (*((volatile unsigned*)&g_barc) < NB) { }
        __threadfence();
    }
    __syncthreads();
}

__global__ void __launch_bounds__(NT, 1) k_fused(
    const float* __restrict__ x,   const int* __restrict__ ei,
    const float* __restrict__ ea,  const int* __restrict__ tgtp,
    const float* __restrict__ Wl1, const float* __restrict__ bl1,
    const float* __restrict__ Wr1, const float* __restrict__ br1,
    const float* __restrict__ We1, const float* __restrict__ att1,
    const float* __restrict__ b1,
    const float* __restrict__ Wl2, const float* __restrict__ bl2,
    const float* __restrict__ Wr2, const float* __restrict__ br2,
    const float* __restrict__ We2, const float* __restrict__ att2,
    const float* __restrict__ b2,
    const float* __restrict__ Wf,  const float* __restrict__ bf,
    float* __restrict__ out)
{
    const int tid  = threadIdx.x;
    const int bid  = blockIdx.x;
    const int lane = tid & 31;
    const int wid  = tid >> 5;
    const int gid  = bid * NT + tid;
    const int c0 = lane, c1 = lane + 32;

    // big buffer: hash (8KB keys + 8KB slots) + local packs (8KB); F alias
    __shared__ __align__(16) char s_big[MAX_DEG2 * C * 4];
    int*    s_hkey  = (int*)s_big;
    int*    s_hslot = (int*)(s_big + HSIZE * 4);
    float4* s_pack  = (float4*)(s_big + 2 * HSIZE * 4);
    float*  s_xl    = (float*)s_big;

    __shared__ float s_w[NWB];
    __shared__ float s_xr[C];
    __shared__ float s_h2[C];
    __shared__ float s_sc[MAX_DEG2];
    __shared__ float s_Wl[2 * C], s_Wr[2 * C], s_We[C], s_att[C], s_bl[C], s_br[C];
    __shared__ int   s_lcnt;
    __shared__ float s_easum;
    __shared__ int   s_elect;

    const int tgt = tgtp[0];
    const int4*   dst4 = reinterpret_cast<const int4*>(ei + EE);
    const float4* ea4  = reinterpret_cast<const float4*>(ea);
    const int stride = NB * NT;

    // dst values held in REGISTERS across the barrier (u=0,1 always valid)
    int4 d0, d1, d2;
    const bool v2 = (gid + 2 * stride) < EV;

    // ---- phase A: straight-line load of this thread's 3 int4 + 3 float4 ---
    {
        if (bid == 0 && tid == 0) {
            if (atomicCAS(&g_slot[tgt], 0, -1) == 0) {
                int p = atomicAdd(&g_s1cnt, 1);
                if (p < MAX_S1) g_s1[p] = tgt;
            }
        }
        float4 a0 = ea4[gid];
        float4 a1 = ea4[gid + stride];
        float4 a2 = v2 ? ea4[gid + 2 * stride] : make_float4(0.f, 0.f, 0.f, 0.f);
        d0 = dst4[gid];
        d1 = dst4[gid + stride];
        d2 = v2 ? dst4[gid + 2 * stride] : make_int4(-1, -1, -1, -1);

        float v = ((a0.x + a0.y) + (a0.z + a0.w))
                + ((a1.x + a1.y) + (a1.z + a1.w))
                + ((a2.x + a2.y) + (a2.z + a2.w));

        // target detection on register-held dsts
        {
            int ivals[12] = {d0.x, d0.y, d0.z, d0.w, d1.x, d1.y, d1.z, d1.w,
                             d2.x, d2.y, d2.z, d2.w};
#pragma unroll
            for (int k = 0; k < 12; k++) {
                if (ivals[k] == tgt) {
                    int e = (gid + (k >> 2) * stride) * 4 + (k & 3);
                    int p = atomicAdd(&g_l2cnt, 1);
                    if (p < MAX_L2) g_l2e[p] = e;
                    int src = ei[e];
                    if (atomicCAS(&g_slot[src], 0, -1) == 0) {
                        int s = atomicAdd(&g_s1cnt, 1);
                        if (s < MAX_S1) g_s1[s] = src;
                    }
                }
            }
        }

        // overlap with load drain: layer-1 weights + hash-table clear
        if (tid < C) {
            s_Wl[tid] = Wl1[tid]; s_Wl[C + tid] = Wl1[C + tid];
            s_Wr[tid] = Wr1[tid]; s_Wr[C + tid] = Wr1[C + tid];
            s_We[tid] = We1[tid]; s_att[tid] = att1[tid];
            s_bl[tid] = bl1[tid]; s_br[tid] = br1[tid];
        }
        for (int i = tid; i < HSIZE; i += NT) s_hkey[i] = -1;
        if (tid == 0) s_lcnt = 0;

        v = wred(v);
        if (lane == 0) s_w[wid] = v;
        __syncthreads();
        if (tid == 0) {
            float s = 0.f;
#pragma unroll
            for (int w = 0; w < NWB; w++) s += s_w[w];
            g_eapart[bid] = s;
        }
    }
    gbar0();

    const int  sc1      = min(g_s1cnt, MAX_S1);
    const bool use_hash = (sc1 <= HASH_CAP);

    // ---- phase B (block 0 only, concurrent with other blocks' phase C) ----
    if (bid == 0) {
        if (wid == 0) {
            float s = 0.f;
            for (int i = lane; i < NB; i += 32) s += g_eapart[i];
            s = wred(s);
            if (lane == 0) { g_easum = s; s_easum = s; }
        }
        for (int i = tid; i < sc1; i += NT) g_slot[g_s1[i]] = i + 1;
        __syncthreads();
        float eam = s_easum * (1.f / (float)EE);
        for (int s = wid; s < sc1; s += NWB) {
            int nd = g_s1[s];
            float x0 = x[2 * nd], x1 = x[2 * nd + 1];
            float xl0 = x0 * s_Wl[c0] + x1 * s_Wl[C + c0] + s_bl[c0];
            float xr0 = x0 * s_Wr[c0] + x1 * s_Wr[C + c0] + s_br[c0];
            float xl1 = x0 * s_Wl[c1] + x1 * s_Wl[C + c1] + s_bl[c1];
            float xr1 = x0 * s_Wr[c1] + x1 * s_Wr[C + c1] + s_br[c1];
            g_xr[s * C + c0] = xr0;
            g_xr[s * C + c1] = xr1;
            float t0 = xl0 + xr0 + eam * s_We[c0];
            float t1 = xl1 + xr1 + eam * s_We[c1];
            t0 = t0 >= 0.f ? t0 : NEG * t0;
            t1 = t1 >= 0.f ? t1 : NEG * t1;
            float scv = wred(t0 * s_att[c0] + t1 * s_att[c1]);
            float w = expf(scv);
            g_nacc[s * C + c0] = w * xl0;
            g_nacc[s * C + c1] = w * xl1;
            if (lane == 0) g_ndenom[s] = w;
        }
        __syncthreads();
        if (tid == 0) { __threadfence(); atomicExch(&g_bflag, 1u); }
    } else if (bid == 1) {
        // warm layer-2 + head weights into L2 for the tail
        float wv = 0.f;
        for (int i = tid; i < C * C; i += NT) wv += Wl2[i] + Wr2[i];
        for (int i = tid; i < C * HIDN; i += NT) wv += Wf[i];
        if (tid < C) wv += We2[tid] + att2[tid] + b2[tid] + b1[tid] + bl2[tid] + br2[tid];
        if (tid < HIDN) wv += bf[tid];
        if (wv == 1.2345678e30f) g_warmsink = wv;
    }

    // ---- phase C: probe REGISTER-HELD dsts (no global re-read) ------------
    {
        if (use_hash) {
            for (int i = tid; i < sc1; i += NT) {
                int v = g_s1[i];
                unsigned h = hh(v);
                while (atomicCAS(&s_hkey[h], -1, v) != -1) h = (h + 1) & HMASK;
                s_hslot[h] = i;
            }
        } else {
            if (tid == 0) {
                while (*((volatile unsigned*)&g_bflag) == 0u) { }
                __threadfence();
            }
        }
        __syncthreads();

        int ivals[12] = {d0.x, d0.y, d0.z, d0.w, d1.x, d1.y, d1.z, d1.w,
                         d2.x, d2.y, d2.z, d2.w};
#pragma unroll
        for (int k = 0; k < 12; k++) {
            int dstv = ivals[k];
            if (k >= 8 && !v2) break;
            int slot;
            if (use_hash) {
                slot = -1;
                unsigned h = hh(dstv);
                while (true) {
                    int e = s_hkey[h];
                    if (e == dstv) { slot = s_hslot[h]; break; }
                    if (e == -1) break;
                    h = (h + 1) & HMASK;
                }
            } else {
                slot = (dstv >= 0 && dstv < NN) ? (g_slot[dstv] - 1) : -1;
            }
            if (slot >= 0) {
                int e = (gid + (k >> 2) * stride) * 4 + (k & 3);
                int srcv = ei[e];
                float eav = ea[e];
                const float2 xj = *reinterpret_cast<const float2*>(x + 2 * srcv);
                float4 pk = make_float4(xj.x, xj.y, eav, __int_as_float(slot));
                int p = atomicAdd(&s_lcnt, 1);
                if (p < LCAP) s_pack[p] = pk;
                else { int q2 = atomicAdd(&g_l1cnt, 1); if (q2 < MAX_L1) g_l1pack[q2] = pk; }
            }
        }
        __syncthreads();
        // blocks with hits wait for phase-B init, then accumulate
        int cnt = min(s_lcnt, LCAP);
        if (cnt > 0) {
            if (tid == 0) {
                while (*((volatile unsigned*)&g_bflag) == 0u) { }
                __threadfence();
            }
            __syncthreads();
            for (int idx = wid; idx < cnt; idx += NWB) {
                float4 pk = s_pack[idx];
                int slot = __float_as_int(pk.w);
                float xl0 = pk.x * s_Wl[c0] + pk.y * s_Wl[C + c0] + s_bl[c0];
                float xl1 = pk.x * s_Wl[c1] + pk.y * s_Wl[C + c1] + s_bl[c1];
                float t0 = xl0 + g_xr[slot * C + c0] + pk.z * s_We[c0];
                float t1 = xl1 + g_xr[slot * C + c1] + pk.z * s_We[c1];
                t0 = t0 >= 0.f ? t0 : NEG * t0;
                t1 = t1 >= 0.f ? t1 : NEG * t1;
                float scv = wred(t0 * s_att[c0] + t1 * s_att[c1]);
                float w = expf(scv);
                atomicAdd(&g_nacc[slot * C + c0], w * xl0);
                atomicAdd(&g_nacc[slot * C + c1], w * xl1);
                if (lane == 0) atomicAdd(&g_ndenom[slot], w);
            }
        }
    }

    // ---- election: LAST block to finish runs the tail ---------------------
    __syncthreads();
    if (tid == 0) {
        __threadfence();
        unsigned t = atomicAdd(&g_done, 1u);
        s_elect = (t == NB - 1u) ? 1 : 0;
        if (s_elect) __threadfence();
    }
    __syncthreads();
    if (!s_elect) return;

    // process global spill packs (normally zero)
    {
        int m1 = min(g_l1cnt, MAX_L1);
        for (int idx = wid; idx < m1; idx += NWB) {
            float4 pk = g_l1pack[idx];
            int slot = __float_as_int(pk.w);
            float xl0 = pk.x * s_Wl[c0] + pk.y * s_Wl[C + c0] + s_bl[c0];
            float xl1 = pk.x * s_Wl[c1] + pk.y * s_Wl[C + c1] + s_bl[c1];
            float t0 = xl0 + g_xr[slot * C + c0] + pk.z * s_We[c0];
            float t1 = xl1 + g_xr[slot * C + c1] + pk.z * s_We[c1];
            t0 = t0 >= 0.f ? t0 : NEG * t0;
            t1 = t1 >= 0.f ? t1 : NEG * t1;
            float scv = wred(t0 * s_att[c0] + t1 * s_att[c1]);
            float w = expf(scv);
            atomicAdd(&g_nacc[slot * C + c0], w * xl0);
            atomicAdd(&g_nacc[slot * C + c1], w * xl1);
            if (lane == 0) atomicAdd(&g_ndenom[slot], w);
        }
    }
    __syncthreads();

    // finalize h1 = relu(acc/denom + b1)
    for (int i = tid; i < sc1 * C; i += NT) {
        float v = g_nacc[i] / g_ndenom[i >> 6] + b1[i & 63];
        g_h1[i] = fmaxf(v, 0.f);
    }
    __syncthreads();

    const int   ts      = g_slot[tgt] - 1;
    const float ea_mean = g_easum * (1.f / (float)EE);

    if (tid < C) {
        const float* h1t = &g_h1[ts * C];
        float a0 = 0.f, a1 = 0.f, a2 = 0.f, a3 = 0.f;
#pragma unroll
        for (int k = 0; k < C; k += 4) {
            a0 += h1t[k]     * Wr2[(k)     * C + tid];
            a1 += h1t[k + 1] * Wr2[(k + 1) * C + tid];
            a2 += h1t[k + 2] * Wr2[(k + 2) * C + tid];
            a3 += h1t[k + 3] * Wr2[(k + 3) * C + tid];
        }
        s_xr[tid] = br2[tid] + ((a0 + a1) + (a2 + a3));
    }
    __syncthreads();

    const int m2  = min(g_l2cnt, MAX_L2);
    const int deg = min(m2 + 1, MAX_DEG2);
    for (int idx = wid; idx < deg; idx += NWB) {
        int j; float eav;
        if (idx == 0) { j = tgt; eav = ea_mean; }
        else          { int e = g_l2e[idx - 1]; j = ei[e]; eav = ea[e]; }
        const float* hrow = &g_h1[(g_slot[j] - 1) * C];
        float xla = bl2[c0], xlb = bl2[c1];
#pragma unroll 8
        for (int k = 0; k < C; k++) {
            float h = hrow[k];
            xla += h * Wl2[k * C + c0];
            xlb += h * Wl2[k * C + c1];
        }
        float ta = xla + s_xr[c0] + eav * We2[c0];
        float tb = xlb + s_xr[c1] + eav * We2[c1];
        ta = ta >= 0.f ? ta : NEG * ta;
        tb = tb >= 0.f ? tb : NEG * tb;
        float s = wred(ta * att2[c0] + tb * att2[c1]);
        s_xl[idx * C + c0] = xla;
        s_xl[idx * C + c1] = xlb;
        if (lane == 0) s_sc[idx] = s;
    }
    __syncthreads();

    if (tid < C) {
        float smax = -3.4e38f;
        for (int k = 0; k < deg; k++) smax = fmaxf(smax, s_sc[k]);
        float denom = 0.f, acc = 0.f;
        for (int k = 0; k < deg; k++) {
            float w = expf(s_sc[k] - smax);
            denom += w;
            acc   += w * s_xl[k * C + tid];
        }
        s_h2[tid] = fmaxf(acc / denom + b2[tid], 0.f);
    }
    __syncthreads();

    if (tid < HIDN) {
        float o = bf[tid];
#pragma unroll
        for (int k = 0; k < C; k++) o += s_h2[k] * Wf[k * HIDN + tid];
        out[tid] = o;
    }

    // ---- cleanup: restore zero-state for graph replay ---------------------
    __syncthreads();
    for (int i = tid; i < sc1; i += NT) g_slot[g_s1[i]] = 0;
    __syncthreads();
    if (tid == 0) {
        g_l2cnt = 0; g_s1cnt = 0; g_l1cnt = 0;
        g_barc = 0; g_bflag = 0; g_done = 0;
        __threadfence();
    }
}

extern "C" void kernel_launch(void* const* d_in, const int* in_sizes, int n_in,
                              void* d_out, int out_size) {
    const float* x    = (const float*)d_in[0];
    const int*   ei   = (const int*)d_in[1];
    const float* ea   = (const float*)d_in[2];
    const int*   tgt  = (const int*)d_in[3];
    const float* Wl1  = (const float*)d_in[4];
    const float* bl1  = (const float*)d_in[5];
    const float* Wr1  = (const float*)d_in[6];
    const float* br1  = (const float*)d_in[7];
    const float* We1  = (const float*)d_in[8];
    const float* att1 = (const float*)d_in[9];
    const float* b1   = (const float*)d_in[10];
    const float* Wl2  = (const float*)d_in[11];
    const float* bl2  = (const float*)d_in[12];
    const float* Wr2  = (const float*)d_in[13];
    const float* br2  = (const float*)d_in[14];
    const float* We2  = (const float*)d_in[15];
    const float* att2 = (const float*)d_in[16];
    const float* b2   = (const float*)d_in[17];
    const float* Wf   = (const float*)d_in[18];
    const float* bf   = (const float*)d_in[19];
    float* out = (float*)d_out;

    k_fused<<<NB, NT>>>(x, ei, ea, tgt,
                        Wl1, bl1, Wr1, br1, We1, att1, b1,
                        Wl2, bl2, Wr2, br2, We2, att2, b2,
                        Wf, bf, out);
}